// round 16
// baseline (speedup 1.0000x reference)
#include <cuda_runtime.h>
#include <cstdint>

#define N_NODES 50000
#define N_EDGES 800000
#define N_GRAPHS 64
#define HID 64
#define HEADS 4
#define LAT 32
#define FEAT 256   // HEADS*HID

// ---------------- scratch (device globals; no allocation) ----------------
__device__ float g_xl[N_NODES * FEAT];      // 51.2 MB
__device__ float g_xr[N_NODES * FEAT];      // 51.2 MB
__device__ float g_h[N_NODES * HID];        // current node features
__device__ int   g_src[N_EDGES];
__device__ int   g_dst[N_EDGES];
__device__ int   g_esrc[N_EDGES];           // src ids, edges sorted by dst
__device__ int   g_deg[N_NODES];            // zeroed at end of each replay (scatter)
__device__ int   g_scan[49 * 1024];         // 50176 >= N_NODES
__device__ int   g_bsum[64];
__device__ int   g_off[N_NODES + 1];        // CSR offsets by dst
__device__ int   g_cur[N_NODES];            // scatter cursors
__device__ float g_pooled[N_GRAPHS * HID];

// ---------------- prep + histogram fused ----------------
__global__ void prep_hist_kernel(const int* __restrict__ ei) {
    int i = blockIdx.x * 256 + threadIdx.x;
    if (i < N_EDGES) {
        g_src[i] = ei[i];
        int d = ei[N_EDGES + i];
        g_dst[i] = d;
        atomicAdd(&g_deg[d], 1);
    }
    if (i < N_GRAPHS * HID) g_pooled[i] = 0.f;
}

// ---- scan over g_deg -> g_off (exclusive), g_cur = g_off ----
__global__ void scan1_kernel() {
    __shared__ int sm[1024];
    int t = threadIdx.x, i = blockIdx.x * 1024 + t;
    int v = (i < N_NODES) ? g_deg[i] : 0;
    sm[t] = v;
    __syncthreads();
    for (int ofs = 1; ofs < 1024; ofs <<= 1) {
        int x = (t >= ofs) ? sm[t - ofs] : 0;
        __syncthreads();
        sm[t] += x;
        __syncthreads();
    }
    g_scan[i] = sm[t];
    if (t == 1023) g_bsum[blockIdx.x] = sm[1023];
}

__global__ void scan23_kernel() {
    __shared__ int sb[64];
    int t = threadIdx.x;
    if (t < 64) sb[t] = (t < 49) ? g_bsum[t] : 0;
    __syncthreads();
    for (int ofs = 1; ofs < 64; ofs <<= 1) {
        int x = 0;
        if (t < 64 && t >= ofs) x = sb[t - ofs];
        __syncthreads();
        if (t < 64) sb[t] += x;
        __syncthreads();
    }
    int i = blockIdx.x * 256 + t;
    if (i < N_NODES) {
        int b = i >> 10;
        int boff = (b == 0) ? 0 : sb[b - 1];
        g_off[i + 1] = g_scan[i] + boff;
        int o = 0;
        if (i > 0) {
            int b2 = (i - 1) >> 10;
            o = g_scan[i - 1] + ((b2 == 0) ? 0 : sb[b2 - 1]);
        }
        g_cur[i] = o;
        if (i == 0) g_off[0] = 0;
    }
}

__global__ void scatter_kernel() {
    int e = blockIdx.x * 256 + threadIdx.x;
    if (e < N_EDGES) {
        int d = g_dst[e];
        int pos = atomicAdd(&g_cur[d], 1);
        g_esrc[pos] = g_src[e];
    }
    if (e < N_NODES) g_deg[e] = 0;   // reset for next graph replay
}

// ---------------- GEMM: O = A @ W via packed fma.rn.f32x2 ----------------
template <int K>
__global__ void __launch_bounds__(256)
gemm_kernel(const float* __restrict__ xext, int use_h,
            const float* __restrict__ W0, const float* __restrict__ W1) {
    const float* __restrict__ A = use_h ? g_h : xext;
    const float* __restrict__ W = blockIdx.y ? W1 : W0;
    float* __restrict__ O = blockIdx.y ? g_xr : g_xl;

    __shared__ float sAT[K][68];   // [k][row], 64 rows + 4 pad

    const int row0 = blockIdx.x * 64;
    const int tid = threadIdx.x;
    const int KQ = K / 4;

    for (int idx = tid; idx < 64 * KQ; idx += 256) {
        int r = idx / KQ, kq = idx % KQ;       // warp = contiguous kq, coalesced
        float4 v = make_float4(0.f, 0.f, 0.f, 0.f);
        if (row0 + r < N_NODES)
            v = *(const float4*)(A + (size_t)(row0 + r) * K + kq * 4);
        sAT[kq * 4 + 0][r] = v.x;
        sAT[kq * 4 + 1][r] = v.y;
        sAT[kq * 4 + 2][r] = v.z;
        sAT[kq * 4 + 3][r] = v.w;
    }
    __syncthreads();

    const int tx = tid & 63;   // cols [tx*4, tx*4+4)
    const int ty = tid >> 6;   // rows [ty*16, ty*16+16)

    unsigned long long accp[8][4];
#pragma unroll
    for (int i = 0; i < 8; i++)
#pragma unroll
        for (int c = 0; c < 4; c++) accp[i][c] = 0ull;

    const float* __restrict__ Wc = W + tx * 4;
#pragma unroll 2
    for (int k = 0; k < K; k++) {
        float4 w = *(const float4*)(Wc + (size_t)k * FEAT);
        unsigned long long wd[4];
        asm("mov.b64 %0, {%1,%1};" : "=l"(wd[0]) : "f"(w.x));
        asm("mov.b64 %0, {%1,%1};" : "=l"(wd[1]) : "f"(w.y));
        asm("mov.b64 %0, {%1,%1};" : "=l"(wd[2]) : "f"(w.z));
        asm("mov.b64 %0, {%1,%1};" : "=l"(wd[3]) : "f"(w.w));

        const ulonglong2* ap = (const ulonglong2*)(&sAT[k][ty * 16]);
        ulonglong2 p0 = ap[0], p1 = ap[1], p2 = ap[2], p3 = ap[3];
        unsigned long long a[8] = {p0.x, p0.y, p1.x, p1.y, p2.x, p2.y, p3.x, p3.y};
#pragma unroll
        for (int i = 0; i < 8; i++)
#pragma unroll
            for (int c = 0; c < 4; c++)
                asm("fma.rn.f32x2 %0, %1, %2, %0;"
                    : "+l"(accp[i][c]) : "l"(a[i]), "l"(wd[c]));
    }

#pragma unroll
    for (int i = 0; i < 8; i++) {
        float lo[4], hi[4];
#pragma unroll
        for (int c = 0; c < 4; c++)
            asm("mov.b64 {%0,%1}, %2;" : "=f"(lo[c]), "=f"(hi[c]) : "l"(accp[i][c]));
        int r_lo = row0 + ty * 16 + 2 * i;
        float4 vlo = make_float4(lo[0], lo[1], lo[2], lo[3]);
        float4 vhi = make_float4(hi[0], hi[1], hi[2], hi[3]);
        if (r_lo < N_NODES)
            *(float4*)(O + (size_t)r_lo * FEAT + tx * 4) = vlo;
        if (r_lo + 1 < N_NODES)
            *(float4*)(O + (size_t)(r_lo + 1) * FEAT + tx * 4) = vhi;
    }
}

// ---------------- fused GATv2 layer with cp.async double buffering ----------
// Warp per dst node. lane = grp*8+gl covers features [grp*64+gl*8, +8).
// Each lane async-copies ITS OWN 32B slice of the next edge's xl row into
// smem stage st^1 while computing the current edge from stage st.
// Per-lane self-consistent slices -> wait_group alone suffices (no syncwarp).

__device__ __forceinline__ void cp16(uint32_t saddr, const void* gaddr) {
    asm volatile("cp.async.cg.shared.global [%0], [%1], 16;"
                 :: "r"(saddr), "l"(gaddr));
}

#define GAT_LOGIT(Lv, A0, A1)                                              \
    {                                                                      \
        float e_, q_ = 0.f;                                                \
        e_ = A0.x + r0.x; e_ = e_ > 0.f ? e_ : 0.2f * e_; q_ += e_ * t0.x; \
        e_ = A0.y + r0.y; e_ = e_ > 0.f ? e_ : 0.2f * e_; q_ += e_ * t0.y; \
        e_ = A0.z + r0.z; e_ = e_ > 0.f ? e_ : 0.2f * e_; q_ += e_ * t0.z; \
        e_ = A0.w + r0.w; e_ = e_ > 0.f ? e_ : 0.2f * e_; q_ += e_ * t0.w; \
        e_ = A1.x + r1.x; e_ = e_ > 0.f ? e_ : 0.2f * e_; q_ += e_ * t1.x; \
        e_ = A1.y + r1.y; e_ = e_ > 0.f ? e_ : 0.2f * e_; q_ += e_ * t1.y; \
        e_ = A1.z + r1.z; e_ = e_ > 0.f ? e_ : 0.2f * e_; q_ += e_ * t1.z; \
        e_ = A1.w + r1.w; e_ = e_ > 0.f ? e_ : 0.2f * e_; q_ += e_ * t1.w; \
        Lv = q_;                                                           \
    }

#define GAT_UPDATE(Lv, A0, A1)                  \
    {                                           \
        float mn_ = fmaxf(m, Lv);               \
        float sc_ = __expf(m - mn_);            \
        float pw_ = __expf(Lv - mn_);           \
        m = mn_;                                \
        s = s * sc_ + pw_;                      \
        acc[0] = acc[0] * sc_ + pw_ * A0.x;     \
        acc[1] = acc[1] * sc_ + pw_ * A0.y;     \
        acc[2] = acc[2] * sc_ + pw_ * A0.z;     \
        acc[3] = acc[3] * sc_ + pw_ * A0.w;     \
        acc[4] = acc[4] * sc_ + pw_ * A1.x;     \
        acc[5] = acc[5] * sc_ + pw_ * A1.y;     \
        acc[6] = acc[6] * sc_ + pw_ * A1.z;     \
        acc[7] = acc[7] * sc_ + pw_ * A1.w;     \
    }

__global__ void __launch_bounds__(256)
fused_gat_kernel(const float* __restrict__ att, const float* __restrict__ bias,
                 const int* __restrict__ batch, int do_pool, int nlim) {
    __shared__ float sbuf[8][2][FEAT];   // 8 warps x 2 stages x 1KB = 16KB
    int w = threadIdx.x >> 5;
    int d = blockIdx.x * 8 + w;
    if (d >= nlim) return;
    int lane = threadIdx.x & 31;
    int grp = lane >> 3, gl = lane & 7;
    int fb = grp * 64 + gl * 8;

    const float4* __restrict__ xr4 = (const float4*)(g_xr + (size_t)d * FEAT + fb);
    float4 r0 = xr4[0], r1 = xr4[1];
    const float4* __restrict__ at4 = (const float4*)(att + fb);
    float4 t0 = __ldg(at4), t1 = __ldg(at4 + 1);

    float m = -1e30f, s = 0.f;
    float acc[8];
#pragma unroll
    for (int i = 0; i < 8; i++) acc[i] = 0.f;

    int e0 = g_off[d], e1 = g_off[d + 1];
    uint32_t base = (uint32_t)__cvta_generic_to_shared(&sbuf[w][0][fb]);

    int p = e0;
    if (p < e1) {
        int sn = __ldg(&g_esrc[p]);
        const float* gp = g_xl + (size_t)sn * FEAT + fb;
        cp16(base, gp);
        cp16(base + 16, gp + 4);
    }
    asm volatile("cp.async.commit_group;" ::: "memory");

    int st = 0;
    for (; p < e1; p++) {
        int nst = st ^ 1;
        if (p + 1 < e1) {
            int sn = __ldg(&g_esrc[p + 1]);
            const float* gp = g_xl + (size_t)sn * FEAT + fb;
            uint32_t b = base + nst * (FEAT * 4);
            cp16(b, gp);
            cp16(b + 16, gp + 4);
        }
        asm volatile("cp.async.commit_group;" ::: "memory");
        asm volatile("cp.async.wait_group 1;" ::: "memory");

        const float* sp = &sbuf[w][st][fb];
        float4 a0 = *(const float4*)sp;
        float4 a1 = *(const float4*)(sp + 4);

        float L;
        GAT_LOGIT(L, a0, a1);
        L += __shfl_xor_sync(0xffffffffu, L, 1);
        L += __shfl_xor_sync(0xffffffffu, L, 2);
        L += __shfl_xor_sync(0xffffffffu, L, 4);
        GAT_UPDATE(L, a0, a1);
        st = nst;
    }
    asm volatile("cp.async.wait_group 0;" ::: "memory");

    // per-head normalize + fold head-mean, then sum across heads
    float inv = 0.25f / (s + 1e-16f);
#pragma unroll
    for (int i = 0; i < 8; i++) {
        float v = acc[i] * inv;
        v += __shfl_xor_sync(0xffffffffu, v, 8);
        v += __shfl_xor_sync(0xffffffffu, v, 16);
        acc[i] = v;
    }

    if (grp == 0) {
        float out[8];
#pragma unroll
        for (int i = 0; i < 8; i++) {
            float v = acc[i] + bias[gl * 8 + i];
            out[i] = v > 0.f ? v : 0.1f * v;
        }
        float4* hp = (float4*)(g_h + (size_t)d * HID + gl * 8);
        hp[0] = make_float4(out[0], out[1], out[2], out[3]);
        hp[1] = make_float4(out[4], out[5], out[6], out[7]);
        if (do_pool) {
            int gph = batch[d];
            float* pp = g_pooled + gph * HID + gl * 8;
#pragma unroll
            for (int i = 0; i < 8; i++) atomicAdd(pp + i, out[i]);
        }
    }
}

// ---------------- BN over graphs + FC, single block ----------------
__global__ void bn_fc_kernel(const float* __restrict__ gamma,
                             const float* __restrict__ beta,
                             const float* __restrict__ fcW,
                             const float* __restrict__ fcb,
                             float* __restrict__ out) {
    __shared__ float snorm[N_GRAPHS * HID];
    int tid = threadIdx.x;
    if (tid < HID) {
        float s = 0.f;
        for (int g = 0; g < N_GRAPHS; g++) s += g_pooled[g * HID + tid];
        float mean = s * (1.f / N_GRAPHS);
        float vs = 0.f;
        for (int g = 0; g < N_GRAPHS; g++) {
            float dlt = g_pooled[g * HID + tid] - mean;
            vs += dlt * dlt;
        }
        float inv = rsqrtf(vs * (1.f / N_GRAPHS) + 1e-5f);
        float ga = gamma[tid] * inv, be = beta[tid];
        for (int g = 0; g < N_GRAPHS; g++)
            snorm[g * HID + tid] = (g_pooled[g * HID + tid] - mean) * ga + be;
    }
    __syncthreads();
    for (int i = tid; i < N_GRAPHS * LAT; i += blockDim.x) {
        int g = i >> 5, l = i & 31;
        float s = fcb[l];
#pragma unroll
        for (int d = 0; d < HID; d++) s += snorm[g * HID + d] * fcW[l * HID + d];
        out[i] = s;
    }
}

// ---------------- launch ----------------
// Launch index 3 (the ncu capture slot) carries a 1/8-size fused_gat PROBE:
// it reads prev-replay xl/xr/esrc (deterministic across replays; zeros on the
// first correctness call) and its g_h output is fully overwritten by the real
// layer-0 fused_gat later. Costs ~25us; buys the gat stall profile.
extern "C" void kernel_launch(void* const* d_in, const int* in_sizes, int n_in,
                              void* d_out, int out_size) {
    const float* x = (const float*)d_in[0];
    const int* ei = (const int*)d_in[1];
    const int* batch = (const int*)d_in[2];
    const float* Wl[3]  = {(const float*)d_in[3],  (const float*)d_in[7],  (const float*)d_in[11]};
    const float* Wr[3]  = {(const float*)d_in[4],  (const float*)d_in[8],  (const float*)d_in[12]};
    const float* att[3] = {(const float*)d_in[5],  (const float*)d_in[9],  (const float*)d_in[13]};
    const float* bb[3]  = {(const float*)d_in[6],  (const float*)d_in[10], (const float*)d_in[14]};
    const float* gamma = (const float*)d_in[15];
    const float* beta  = (const float*)d_in[16];
    const float* fcW   = (const float*)d_in[17];
    const float* fcb   = (const float*)d_in[18];
    float* out = (float*)d_out;

    const int eb = (N_EDGES + 255) / 256;           // 3125
    const int gemm_bx = (N_NODES + 63) / 64;        // 782
    const int gat_b = (N_NODES + 7) / 8;            // 6250, warp per node
    const int probe_n = N_NODES / 8;                // 6250 nodes
    const int probe_b = (probe_n + 7) / 8;          // 782 blocks
    const int nb = (N_NODES + 255) / 256;

    prep_hist_kernel<<<eb, 256>>>(ei);                                  // 0
    scan1_kernel<<<49, 1024>>>();                                       // 1
    scan23_kernel<<<nb, 256>>>();                                       // 2
    fused_gat_kernel<<<probe_b, 256>>>(att[0], bb[0], batch, 0, probe_n); // 3 <- profiled
    scatter_kernel<<<eb, 256>>>();                                      // 4

    gemm_kernel<128><<<dim3(gemm_bx, 2), 256>>>(x, 0, Wl[0], Wr[0]);    // 5
    fused_gat_kernel<<<gat_b, 256>>>(att[0], bb[0], batch, 0, N_NODES); // 6

    for (int l = 1; l < 3; l++) {
        gemm_kernel<64><<<dim3(gemm_bx, 2), 256>>>(nullptr, 1, Wl[l], Wr[l]);
        fused_gat_kernel<<<gat_b, 256>>>(att[l], bb[l], batch, l == 2 ? 1 : 0, N_NODES);
    }

    bn_fc_kernel<<<1, 256>>>(gamma, beta, fcW, fcb, out);
}

// round 17
// speedup vs baseline: 1.0229x; 1.0229x over previous
#include <cuda_runtime.h>
#include <cstdint>

#define N_NODES 50000
#define N_EDGES 800000
#define N_GRAPHS 64
#define HID 64
#define HEADS 4
#define LAT 32
#define FEAT 256   // HEADS*HID

// ---------------- scratch (device globals; no allocation) ----------------
__device__ float g_xl[N_NODES * FEAT];      // 51.2 MB
__device__ float g_xr[N_NODES * FEAT];      // 51.2 MB
__device__ float g_h[N_NODES * HID];        // current node features
__device__ int   g_src[N_EDGES];
__device__ int   g_dst[N_EDGES];
__device__ int   g_esrc[N_EDGES];           // src ids, edges sorted by dst
__device__ int   g_deg[N_NODES];            // zeroed at end of each replay (scatter)
__device__ int   g_scan[49 * 1024];         // 50176 >= N_NODES
__device__ int   g_bsum[64];
__device__ int   g_off[N_NODES + 1];        // CSR offsets by dst
__device__ int   g_cur[N_NODES];            // scatter cursors
__device__ float g_pooled[N_GRAPHS * HID];

__device__ __forceinline__ void cp16(uint32_t saddr, const void* gaddr) {
    asm volatile("cp.async.cg.shared.global [%0], [%1], 16;"
                 :: "r"(saddr), "l"(gaddr));
}

// ---------------- prep + histogram fused ----------------
__global__ void prep_hist_kernel(const int* __restrict__ ei) {
    int i = blockIdx.x * 256 + threadIdx.x;
    if (i < N_EDGES) {
        g_src[i] = ei[i];
        int d = ei[N_EDGES + i];
        g_dst[i] = d;
        atomicAdd(&g_deg[d], 1);
    }
    if (i < N_GRAPHS * HID) g_pooled[i] = 0.f;
}

// ---- scan over g_deg -> g_off (exclusive), g_cur = g_off ----
__global__ void scan1_kernel() {
    __shared__ int sm[1024];
    int t = threadIdx.x, i = blockIdx.x * 1024 + t;
    int v = (i < N_NODES) ? g_deg[i] : 0;
    sm[t] = v;
    __syncthreads();
    for (int ofs = 1; ofs < 1024; ofs <<= 1) {
        int x = (t >= ofs) ? sm[t - ofs] : 0;
        __syncthreads();
        sm[t] += x;
        __syncthreads();
    }
    g_scan[i] = sm[t];
    if (t == 1023) g_bsum[blockIdx.x] = sm[1023];
}

__global__ void scan23_kernel() {
    __shared__ int sb[64];
    int t = threadIdx.x;
    if (t < 64) sb[t] = (t < 49) ? g_bsum[t] : 0;
    __syncthreads();
    for (int ofs = 1; ofs < 64; ofs <<= 1) {
        int x = 0;
        if (t < 64 && t >= ofs) x = sb[t - ofs];
        __syncthreads();
        if (t < 64) sb[t] += x;
        __syncthreads();
    }
    int i = blockIdx.x * 256 + t;
    if (i < N_NODES) {
        int b = i >> 10;
        int boff = (b == 0) ? 0 : sb[b - 1];
        g_off[i + 1] = g_scan[i] + boff;
        int o = 0;
        if (i > 0) {
            int b2 = (i - 1) >> 10;
            o = g_scan[i - 1] + ((b2 == 0) ? 0 : sb[b2 - 1]);
        }
        g_cur[i] = o;
        if (i == 0) g_off[0] = 0;
    }
}

__global__ void scatter_kernel() {
    int e = blockIdx.x * 256 + threadIdx.x;
    if (e < N_EDGES) {
        int d = g_dst[e];
        int pos = atomicAdd(&g_cur[d], 1);
        g_esrc[pos] = g_src[e];
    }
    if (e < N_NODES) g_deg[e] = 0;   // reset for next graph replay
}

// ---------------- GEMM: O = A @ W, f32x2 FMA + cp.async W staging ----------
// Tile: 64 rows x 256 cols, 256 threads; thread = (tx: 4 cols, ty: 16 rows).
// W streamed through smem in 16-k double-buffered chunks (cp.async) so the
// mainloop has NO global-latency dependence; A transposed in smem (pad 66:
// 8-way STS conflicts, LDS.64 broadcast reads, 8B-aligned rows).
template <int K>
__global__ void __launch_bounds__(256)
gemm_kernel(const float* __restrict__ xext, int use_h,
            const float* __restrict__ W0, const float* __restrict__ W1) {
    extern __shared__ float dyn[];
    float (*sAT)[66] = (float (*)[66])dyn;                       // [K][66]
    float (*sW)[16][256] = (float (*)[16][256])(dyn + K * 66);   // [2][16][256]

    const float* __restrict__ A = use_h ? g_h : xext;
    const float* __restrict__ W = blockIdx.y ? W1 : W0;
    float* __restrict__ O = blockIdx.y ? g_xr : g_xl;

    const int row0 = blockIdx.x * 64;
    const int tid = threadIdx.x;
    const int KQ = K / 4;

    // prefetch W chunk 0 (overlaps the A-tile LDGs below)
    for (int i = tid; i < 1024; i += 256) {
        int kr = i >> 6, c4 = i & 63;
        cp16((uint32_t)__cvta_generic_to_shared(&sW[0][kr][c4 * 4]),
             W + (size_t)kr * FEAT + c4 * 4);
    }
    asm volatile("cp.async.commit_group;" ::: "memory");

    // A tile, transposed: warp covers contiguous kq of one row -> coalesced LDG
    for (int idx = tid; idx < 64 * KQ; idx += 256) {
        int r = idx / KQ, kq = idx % KQ;
        float4 v = make_float4(0.f, 0.f, 0.f, 0.f);
        if (row0 + r < N_NODES)
            v = *(const float4*)(A + (size_t)(row0 + r) * K + kq * 4);
        sAT[kq * 4 + 0][r] = v.x;
        sAT[kq * 4 + 1][r] = v.y;
        sAT[kq * 4 + 2][r] = v.z;
        sAT[kq * 4 + 3][r] = v.w;
    }
    __syncthreads();

    const int tx = tid & 63;   // cols [tx*4, tx*4+4)
    const int ty = tid >> 6;   // rows [ty*16, ty*16+16)

    unsigned long long accp[8][4];   // [row-pair][col]
#pragma unroll
    for (int i = 0; i < 8; i++)
#pragma unroll
        for (int c = 0; c < 4; c++) accp[i][c] = 0ull;

    const int NCH = K / 16;
    for (int ch = 0; ch < NCH; ch++) {
        if (ch + 1 < NCH) {
            for (int i = tid; i < 1024; i += 256) {
                int kr = i >> 6, c4 = i & 63;
                cp16((uint32_t)__cvta_generic_to_shared(&sW[(ch + 1) & 1][kr][c4 * 4]),
                     W + (size_t)((ch + 1) * 16 + kr) * FEAT + c4 * 4);
            }
        }
        asm volatile("cp.async.commit_group;" ::: "memory");
        asm volatile("cp.async.wait_group 1;" ::: "memory");
        __syncthreads();

        const float (*wb)[256] = sW[ch & 1];
#pragma unroll 4
        for (int kk = 0; kk < 16; kk++) {
            int k = ch * 16 + kk;
            float4 w = *(const float4*)&wb[kk][tx * 4];
            unsigned long long wd[4];
            asm("mov.b64 %0, {%1,%1};" : "=l"(wd[0]) : "f"(w.x));
            asm("mov.b64 %0, {%1,%1};" : "=l"(wd[1]) : "f"(w.y));
            asm("mov.b64 %0, {%1,%1};" : "=l"(wd[2]) : "f"(w.z));
            asm("mov.b64 %0, {%1,%1};" : "=l"(wd[3]) : "f"(w.w));

            const unsigned long long* ap =
                (const unsigned long long*)&sAT[k][ty * 16];  // 8B-aligned (264k+64ty)
            unsigned long long a[8];
#pragma unroll
            for (int i = 0; i < 8; i++) a[i] = ap[i];
#pragma unroll
            for (int i = 0; i < 8; i++)
#pragma unroll
                for (int c = 0; c < 4; c++)
                    asm("fma.rn.f32x2 %0, %1, %2, %0;"
                        : "+l"(accp[i][c]) : "l"(a[i]), "l"(wd[c]));
        }
        __syncthreads();   // all reads of sW[ch&1] done before ch+1 overwrites it
    }

#pragma unroll
    for (int i = 0; i < 8; i++) {
        float lo[4], hi[4];
#pragma unroll
        for (int c = 0; c < 4; c++)
            asm("mov.b64 {%0,%1}, %2;" : "=f"(lo[c]), "=f"(hi[c]) : "l"(accp[i][c]));
        int r_lo = row0 + ty * 16 + 2 * i;
        if (r_lo < N_NODES)
            *(float4*)(O + (size_t)r_lo * FEAT + tx * 4) =
                make_float4(lo[0], lo[1], lo[2], lo[3]);
        if (r_lo + 1 < N_NODES)
            *(float4*)(O + (size_t)(r_lo + 1) * FEAT + tx * 4) =
                make_float4(hi[0], hi[1], hi[2], hi[3]);
    }
}

// ---------------- fused GATv2 layer, cp.async ring depth 4 ----------------
// Warp per dst node; lane = grp*8+gl covers features [grp*64+gl*8, +8).
// Lookahead 3 edges: T_iter ~ lat/4 instead of lat/2.

#define GAT_LOGIT(Lv, A0, A1)                                              \
    {                                                                      \
        float e_, q_ = 0.f;                                                \
        e_ = A0.x + r0.x; e_ = e_ > 0.f ? e_ : 0.2f * e_; q_ += e_ * t0.x; \
        e_ = A0.y + r0.y; e_ = e_ > 0.f ? e_ : 0.2f * e_; q_ += e_ * t0.y; \
        e_ = A0.z + r0.z; e_ = e_ > 0.f ? e_ : 0.2f * e_; q_ += e_ * t0.z; \
        e_ = A0.w + r0.w; e_ = e_ > 0.f ? e_ : 0.2f * e_; q_ += e_ * t0.w; \
        e_ = A1.x + r1.x; e_ = e_ > 0.f ? e_ : 0.2f * e_; q_ += e_ * t1.x; \
        e_ = A1.y + r1.y; e_ = e_ > 0.f ? e_ : 0.2f * e_; q_ += e_ * t1.y; \
        e_ = A1.z + r1.z; e_ = e_ > 0.f ? e_ : 0.2f * e_; q_ += e_ * t1.z; \
        e_ = A1.w + r1.w; e_ = e_ > 0.f ? e_ : 0.2f * e_; q_ += e_ * t1.w; \
        Lv = q_;                                                           \
    }

#define GAT_UPDATE(Lv, A0, A1)                  \
    {                                           \
        float mn_ = fmaxf(m, Lv);               \
        float sc_ = __expf(m - mn_);            \
        float pw_ = __expf(Lv - mn_);           \
        m = mn_;                                \
        s = s * sc_ + pw_;                      \
        acc[0] = acc[0] * sc_ + pw_ * A0.x;     \
        acc[1] = acc[1] * sc_ + pw_ * A0.y;     \
        acc[2] = acc[2] * sc_ + pw_ * A0.z;     \
        acc[3] = acc[3] * sc_ + pw_ * A0.w;     \
        acc[4] = acc[4] * sc_ + pw_ * A1.x;     \
        acc[5] = acc[5] * sc_ + pw_ * A1.y;     \
        acc[6] = acc[6] * sc_ + pw_ * A1.z;     \
        acc[7] = acc[7] * sc_ + pw_ * A1.w;     \
    }

__global__ void __launch_bounds__(256)
fused_gat_kernel(const float* __restrict__ att, const float* __restrict__ bias,
                 const int* __restrict__ batch, int do_pool) {
    __shared__ float sbuf[8][4][FEAT];   // 8 warps x 4 stages x 1KB = 32KB
    int w = threadIdx.x >> 5;
    int d = blockIdx.x * 8 + w;
    if (d >= N_NODES) return;
    int lane = threadIdx.x & 31;
    int grp = lane >> 3, gl = lane & 7;
    int fb = grp * 64 + gl * 8;

    const float4* __restrict__ xr4 = (const float4*)(g_xr + (size_t)d * FEAT + fb);
    float4 r0 = __ldcs(xr4), r1 = __ldcs(xr4 + 1);
    const float4* __restrict__ at4 = (const float4*)(att + fb);
    float4 t0 = __ldg(at4), t1 = __ldg(at4 + 1);

    float m = -1e30f, s = 0.f;
    float acc[8];
#pragma unroll
    for (int i = 0; i < 8; i++) acc[i] = 0.f;

    int e0 = g_off[d], e1 = g_off[d + 1];
    uint32_t base = (uint32_t)__cvta_generic_to_shared(&sbuf[w][0][fb]);

    // prologue: stages 0..2 for edges e0..e0+2 (one commit-group per edge)
#pragma unroll
    for (int j = 0; j < 3; j++) {
        if (e0 + j < e1) {
            int sn = __ldg(&g_esrc[e0 + j]);
            const float* gp = g_xl + (size_t)sn * FEAT + fb;
            uint32_t b = base + j * (FEAT * 4);
            cp16(b, gp);
            cp16(b + 16, gp + 4);
        }
        asm volatile("cp.async.commit_group;" ::: "memory");
    }

    for (int p = e0; p < e1; p++) {
        int idx = p - e0;
        if (p + 3 < e1) {
            int sn = __ldg(&g_esrc[p + 3]);
            const float* gp = g_xl + (size_t)sn * FEAT + fb;
            uint32_t b = base + ((idx + 3) & 3) * (FEAT * 4);
            cp16(b, gp);
            cp16(b + 16, gp + 4);
        }
        asm volatile("cp.async.commit_group;" ::: "memory");
        asm volatile("cp.async.wait_group 3;" ::: "memory");  // edge p resident

        const float* sp = &sbuf[w][idx & 3][fb];
        float4 a0 = *(const float4*)sp;
        float4 a1 = *(const float4*)(sp + 4);

        float L;
        GAT_LOGIT(L, a0, a1);
        L += __shfl_xor_sync(0xffffffffu, L, 1);
        L += __shfl_xor_sync(0xffffffffu, L, 2);
        L += __shfl_xor_sync(0xffffffffu, L, 4);
        GAT_UPDATE(L, a0, a1);
    }
    asm volatile("cp.async.wait_group 0;" ::: "memory");

    // per-head normalize + fold head-mean, then sum across heads
    float inv = 0.25f / (s + 1e-16f);
#pragma unroll
    for (int i = 0; i < 8; i++) {
        float v = acc[i] * inv;
        v += __shfl_xor_sync(0xffffffffu, v, 8);
        v += __shfl_xor_sync(0xffffffffu, v, 16);
        acc[i] = v;
    }

    if (grp == 0) {
        float out[8];
#pragma unroll
        for (int i = 0; i < 8; i++) {
            float v = acc[i] + bias[gl * 8 + i];
            out[i] = v > 0.f ? v : 0.1f * v;
        }
        float4* hp = (float4*)(g_h + (size_t)d * HID + gl * 8);
        hp[0] = make_float4(out[0], out[1], out[2], out[3]);
        hp[1] = make_float4(out[4], out[5], out[6], out[7]);
        if (do_pool) {
            int gph = batch[d];
            float* pp = g_pooled + gph * HID + gl * 8;
#pragma unroll
            for (int i = 0; i < 8; i++) atomicAdd(pp + i, out[i]);
        }
    }
}

// ---------------- BN over graphs + FC, single block ----------------
__global__ void bn_fc_kernel(const float* __restrict__ gamma,
                             const float* __restrict__ beta,
                             const float* __restrict__ fcW,
                             const float* __restrict__ fcb,
                             float* __restrict__ out) {
    __shared__ float snorm[N_GRAPHS * HID];
    int tid = threadIdx.x;
    if (tid < HID) {
        float s = 0.f;
        for (int g = 0; g < N_GRAPHS; g++) s += g_pooled[g * HID + tid];
        float mean = s * (1.f / N_GRAPHS);
        float vs = 0.f;
        for (int g = 0; g < N_GRAPHS; g++) {
            float dlt = g_pooled[g * HID + tid] - mean;
            vs += dlt * dlt;
        }
        float inv = rsqrtf(vs * (1.f / N_GRAPHS) + 1e-5f);
        float ga = gamma[tid] * inv, be = beta[tid];
        for (int g = 0; g < N_GRAPHS; g++)
            snorm[g * HID + tid] = (g_pooled[g * HID + tid] - mean) * ga + be;
    }
    __syncthreads();
    for (int i = tid; i < N_GRAPHS * LAT; i += blockDim.x) {
        int g = i >> 5, l = i & 31;
        float s = fcb[l];
#pragma unroll
        for (int d = 0; d < HID; d++) s += snorm[g * HID + d] * fcW[l * HID + d];
        out[i] = s;
    }
}

// ---------------- launch ----------------
// gemm<128> at launch index 3 (the observed ncu capture slot) to verify the
// W-staging rewrite against R11's 159us / fma=52% profile.
extern "C" void kernel_launch(void* const* d_in, const int* in_sizes, int n_in,
                              void* d_out, int out_size) {
    const float* x = (const float*)d_in[0];
    const int* ei = (const int*)d_in[1];
    const int* batch = (const int*)d_in[2];
    const float* Wl[3]  = {(const float*)d_in[3],  (const float*)d_in[7],  (const float*)d_in[11]};
    const float* Wr[3]  = {(const float*)d_in[4],  (const float*)d_in[8],  (const float*)d_in[12]};
    const float* att[3] = {(const float*)d_in[5],  (const float*)d_in[9],  (const float*)d_in[13]};
    const float* bb[3]  = {(const float*)d_in[6],  (const float*)d_in[10], (const float*)d_in[14]};
    const float* gamma = (const float*)d_in[15];
    const float* beta  = (const float*)d_in[16];
    const float* fcW   = (const float*)d_in[17];
    const float* fcb   = (const float*)d_in[18];
    float* out = (float*)d_out;

    const int smem128 = (128 * 66 + 2 * 16 * 256) * 4;   // 66.5KB
    const int smem64  = (64 * 66 + 2 * 16 * 256) * 4;    // 49.7KB
    cudaFuncSetAttribute(gemm_kernel<128>,
                         cudaFuncAttributeMaxDynamicSharedMemorySize, smem128);
    cudaFuncSetAttribute(gemm_kernel<64>,
                         cudaFuncAttributeMaxDynamicSharedMemorySize, smem64);

    const int eb = (N_EDGES + 255) / 256;           // 3125
    const int gemm_bx = (N_NODES + 63) / 64;        // 782
    const int gat_b = (N_NODES + 7) / 8;            // 6250, warp per node
    const int nb = (N_NODES + 255) / 256;

    prep_hist_kernel<<<eb, 256>>>(ei);                                      // 0
    scan1_kernel<<<49, 1024>>>();                                           // 1
    scan23_kernel<<<nb, 256>>>();                                           // 2
    gemm_kernel<128><<<dim3(gemm_bx, 2), 256, smem128>>>(x, 0, Wl[0], Wr[0]); // 3 <- profiled
    scatter_kernel<<<eb, 256>>>();                                          // 4

    fused_gat_kernel<<<gat_b, 256>>>(att[0], bb[0], batch, 0);              // 5

    for (int l = 1; l < 3; l++) {
        gemm_kernel<64><<<dim3(gemm_bx, 2), 256, smem64>>>(nullptr, 1, Wl[l], Wr[l]);
        fused_gat_kernel<<<gat_b, 256>>>(att[l], bb[l], batch, l == 2 ? 1 : 0);
    }

    bn_fc_kernel<<<1, 256>>>(gamma, beta, fcW, fcb, out);
}